// round 1
// baseline (speedup 1.0000x reference)
#include <cuda_runtime.h>
#include <math.h>

// Problem maxima (fixed shapes: n=1024, C=100, D=128, K=4096)
#define D_DIM   128
#define N_MAX   1024
#define C_MAX   128
#define KT_MAX  64          // K/128 tiles (4096/128 = 32 actually used)
#define RCH     32          // rows-per-chunk in main kernel
#define TK      128         // k-tile width

// -------- scratch (device globals; no allocations allowed) --------
__device__ float g_wn  [C_MAX * D_DIM];     // normalized weight rows
__device__ float g_qa  [N_MAX * D_DIM];     // normalized anchor qa per row
__device__ float g_lpos[N_MAX];
__device__ float g_bb  [N_MAX];             // b_i = qa_i . wn_{c_i}
__device__ int   g_off [C_MAX + 1];
__device__ int   g_rows[N_MAX];
__device__ int   g_lstride;                 // 1 = int32 labels, 2 = int64 (low word)
__device__ float g_pm  [N_MAX * KT_MAX];    // partial max   per (row, ktile)
__device__ float g_ps  [N_MAX * KT_MAX];    // partial sumexp per (row, ktile)

__device__ __forceinline__ float warpSum(float v) {
    #pragma unroll
    for (int o = 16; o; o >>= 1) v += __shfl_xor_sync(0xffffffffu, v, o);
    return v;
}

// block (128 threads) sum reduce, result broadcast to all threads
__device__ __forceinline__ float brSum128(float v, float* s4, int t) {
    v = warpSum(v);
    __syncthreads();                 // protect s4 from prior use
    if ((t & 31) == 0) s4[t >> 5] = v;
    __syncthreads();
    return s4[0] + s4[1] + s4[2] + s4[3];
}

// -------- kernel A: normalize weight rows --------
__global__ void norm_w_kernel(const float* __restrict__ weight) {
    int c = blockIdx.x, t = threadIdx.x;
    __shared__ float s4[4];
    float w  = weight[c * D_DIM + t];
    float ss = brSum128(w * w, s4, t);
    g_wn[c * D_DIM + t] = w / fmaxf(sqrtf(ss), 1e-12f);
}

// -------- kernel C: detect label dtype + group rows by class (one block, n threads) --------
__global__ void group_kernel(const int* __restrict__ lab32, int n, int C) {
    __shared__ int cnt[C_MAX];
    __shared__ int base[C_MAX + 1];
    __shared__ int oddnz;
    int t = threadIdx.x;
    if (t == 0) oddnz = 0;
    if (t < C) cnt[t] = 0;
    __syncthreads();
    // int64 detection: stored little-endian, labels < 2^31 => every odd word is 0
    if (t < (n >> 1) && lab32[2 * t + 1] != 0) atomicAdd(&oddnz, 1);
    __syncthreads();
    int stride = (oddnz == 0) ? 2 : 1;
    if (t == 0) g_lstride = stride;
    if (t < n) atomicAdd(&cnt[lab32[t * stride]], 1);
    __syncthreads();
    if (t == 0) {
        base[0] = 0;
        for (int c = 0; c < C; ++c) base[c + 1] = base[c] + cnt[c];
    }
    __syncthreads();
    if (t <= C) g_off[t] = base[t];
    if (t < C)  cnt[t] = 0;
    __syncthreads();
    if (t < n) {
        int c = lab32[t * stride];
        int p = base[c] + atomicAdd(&cnt[c], 1);
        g_rows[p] = t;
    }
}

// -------- kernel B: per-row qa, l_pos, b --------
__global__ void rows_kernel(const float* __restrict__ q,
                            const float* __restrict__ k,
                            const int*   __restrict__ lab32) {
    int i = blockIdx.x, t = threadIdx.x;
    __shared__ float s4[4];
    int c = lab32[i * g_lstride];
    float wv = g_wn[c * D_DIM + t];
    float qv = q[i * D_DIM + t];
    float kv = k[i * D_DIM + t];

    float qn = qv / fmaxf(sqrtf(brSum128(qv * qv, s4, t)), 1e-12f);
    float kn = kv / fmaxf(sqrtf(brSum128(kv * kv, s4, t)), 1e-12f);
    float aq = qn - wv;
    float ak = kn - wv;
    float qa = aq / fmaxf(sqrtf(brSum128(aq * aq, s4, t)), 1e-12f);
    float ka = ak / fmaxf(sqrtf(brSum128(ak * ak, s4, t)), 1e-12f);
    g_qa[i * D_DIM + t] = qa;
    float lp = brSum128(qa * ka, s4, t);
    float bv = brSum128(qa * wv, s4, t);
    if (t == 0) { g_lpos[i] = lp; g_bb[i] = bv; }
}

// -------- kernel D: main fused queue pass --------
// grid = (KT, C), 128 threads. Each block: class c, k-tile kt.
// smem: tile[128][128] + wn[128] + Qs[RCH][128] + Vs[RCH][128] + bs[RCH] + ris[RCH]
__global__ void main_kernel(const float* __restrict__ queue, int K, int KT) {
    const int c  = blockIdx.y;
    const int kt = blockIdx.x;
    const int t  = threadIdx.x;
    const int off = g_off[c];
    const int nc  = g_off[c + 1] - off;
    if (nc == 0) return;

    extern __shared__ float sh[];
    float* tile = sh;                       // 128*128
    float* wns  = tile + 128 * 128;         // 128
    float* Qs   = wns + 128;                // RCH*128
    float* Vs   = Qs + RCH * 128;           // RCH*128
    float* bs   = Vs + RCH * 128;           // RCH
    int*   ris  = (int*)(bs + RCH);         // RCH

    wns[t] = g_wn[c * D_DIM + t];

    // load tile [d][k] coalesced (float4 over k)
    for (int i = t; i < 128 * 32; i += 128) {
        int d  = i >> 5;
        int c4 = i & 31;
        const float4* src =
            (const float4*)(queue + ((size_t)(c * D_DIM + d)) * K + (size_t)kt * TK);
        ((float4*)tile)[d * 32 + c4] = src[c4];
    }
    __syncthreads();

    // per-column stats: ||x||, x.wn, ||wn||^2
    float ss = 0.f, sd = 0.f, w2 = 0.f;
    #pragma unroll 8
    for (int d = 0; d < 128; ++d) {
        float v  = tile[d * 128 + t];
        float wd = wns[d];
        ss = fmaf(v, v, ss);
        sd = fmaf(v, wd, sd);
        w2 = fmaf(wd, wd, w2);
    }
    float inv_nc = 1.f / fmaxf(sqrtf(ss), 1e-12f);
    float na2 = fmaf(ss * inv_nc, inv_nc, fmaf(-2.f * sd, inv_nc, w2));
    float inv_den = 1.f / fmaxf(sqrtf(fmaxf(na2, 0.f)), 1e-12f);
    const float invT = 1.f / 0.07f;
    float sA = inv_nc * inv_den * invT;     // scales raw dot
    float sB = inv_den * invT;              // scales b_i

    const int lane = t & 31, wid = t >> 5;

    for (int r0 = 0; r0 < nc; r0 += RCH) {
        int rn  = min(RCH, nc - r0);
        int rn4 = (rn + 3) & ~3;
        __syncthreads();                    // Qs/Vs done being read from prev iter
        if (t < rn) {
            int ri = g_rows[off + r0 + t];
            ris[t] = ri;
            bs[t]  = g_bb[ri];
        }
        __syncthreads();
        // gather qa rows (zero-pad to multiple of 4)
        for (int i = t; i < rn4 * 32; i += 128) {
            int r  = i >> 5;
            int c4 = i & 31;
            float4 v = make_float4(0.f, 0.f, 0.f, 0.f);
            if (r < rn) v = ((const float4*)(g_qa + (size_t)ris[r] * D_DIM))[c4];
            ((float4*)Qs)[r * 32 + c4] = v;
        }
        __syncthreads();

        // 4-row register-blocked smem GEMM, D unrolled by 4 via float4 broadcast
        for (int r = 0; r < rn4; r += 4) {
            float a0 = 0.f, a1 = 0.f, a2 = 0.f, a3 = 0.f;
            const float4* q0 = (const float4*)(Qs + (r + 0) * 128);
            const float4* q1 = (const float4*)(Qs + (r + 1) * 128);
            const float4* q2 = (const float4*)(Qs + (r + 2) * 128);
            const float4* q3 = (const float4*)(Qs + (r + 3) * 128);
            #pragma unroll
            for (int d4 = 0; d4 < 32; ++d4) {
                float v0 = tile[(d4 * 4 + 0) * 128 + t];
                float v1 = tile[(d4 * 4 + 1) * 128 + t];
                float v2 = tile[(d4 * 4 + 2) * 128 + t];
                float v3 = tile[(d4 * 4 + 3) * 128 + t];
                float4 x0 = q0[d4], x1 = q1[d4], x2 = q2[d4], x3 = q3[d4];
                a0 = fmaf(x0.x, v0, fmaf(x0.y, v1, fmaf(x0.z, v2, fmaf(x0.w, v3, a0))));
                a1 = fmaf(x1.x, v0, fmaf(x1.y, v1, fmaf(x1.z, v2, fmaf(x1.w, v3, a1))));
                a2 = fmaf(x2.x, v0, fmaf(x2.y, v1, fmaf(x2.z, v2, fmaf(x2.w, v3, a2))));
                a3 = fmaf(x3.x, v0, fmaf(x3.y, v1, fmaf(x3.z, v2, fmaf(x3.w, v3, a3))));
            }
            Vs[(r + 0) * 128 + t] = fmaf(a0, sA, -bs[r + 0] * sB);
            Vs[(r + 1) * 128 + t] = fmaf(a1, sA, -bs[r + 1] * sB);
            Vs[(r + 2) * 128 + t] = fmaf(a2, sA, -bs[r + 2] * sB);
            Vs[(r + 3) * 128 + t] = fmaf(a3, sA, -bs[r + 3] * sB);
        }
        __syncthreads();

        // warp-per-row partial logsumexp across the 128 logits of this tile
        for (int r = wid; r < rn; r += 4) {
            float v0 = Vs[r * 128 + lane];
            float v1 = Vs[r * 128 + lane + 32];
            float v2 = Vs[r * 128 + lane + 64];
            float v3 = Vs[r * 128 + lane + 96];
            float m = fmaxf(fmaxf(v0, v1), fmaxf(v2, v3));
            #pragma unroll
            for (int o = 16; o; o >>= 1) m = fmaxf(m, __shfl_xor_sync(0xffffffffu, m, o));
            float s = expf(v0 - m) + expf(v1 - m) + expf(v2 - m) + expf(v3 - m);
            s = warpSum(s);
            if (lane == 0) {
                int ri = ris[r];
                g_pm[ri * KT + kt] = m;
                g_ps[ri * KT + kt] = s;
            }
        }
    }
}

// -------- kernel E: combine partials, logsumexp, mean --------
__global__ void finalize_kernel(float* __restrict__ out, int n, int KT) {
    int t = threadIdx.x;
    const float invT = 1.f / 0.07f;
    float li = 0.f;
    if (t < n) {
        float lp = g_lpos[t] * invT;
        float M = lp;
        for (int j = 0; j < KT; ++j) M = fmaxf(M, g_pm[t * KT + j]);
        float S = expf(lp - M);
        for (int j = 0; j < KT; ++j) S += g_ps[t * KT + j] * expf(g_pm[t * KT + j] - M);
        li = logf(S) + M - lp;
    }
    __shared__ float sm[32];
    float v = warpSum(li);
    if ((t & 31) == 0) sm[t >> 5] = v;
    __syncthreads();
    if (t < 32) {
        int nw = (blockDim.x + 31) >> 5;
        float x = (t < nw) ? sm[t] : 0.f;
        x = warpSum(x);
        if (t == 0) out[0] = x / (float)n;
    }
}

extern "C" void kernel_launch(void* const* d_in, const int* in_sizes, int n_in,
                              void* d_out, int out_size) {
    const float* q      = (const float*)d_in[0];
    const float* k      = (const float*)d_in[1];
    const float* weight = (const float*)d_in[2];
    const int*   lab32  = (const int*)d_in[3];
    const float* queue  = (const float*)d_in[4];

    int n  = in_sizes[0] / D_DIM;                 // 1024
    int C  = in_sizes[2] / D_DIM;                 // 100
    long long qe = in_sizes[4];
    int K  = (int)(qe / ((long long)C * D_DIM));  // 4096
    int KT = K / TK;                              // 32

    const int smem_bytes =
        (128 * 128 + 128 + RCH * 128 + RCH * 128 + RCH) * (int)sizeof(float)
        + RCH * (int)sizeof(int);
    cudaFuncSetAttribute(main_kernel,
                         cudaFuncAttributeMaxDynamicSharedMemorySize, smem_bytes);

    norm_w_kernel<<<C, 128>>>(weight);
    group_kernel<<<1, n>>>(lab32, n, C);
    rows_kernel<<<n, 128>>>(q, k, lab32);
    main_kernel<<<dim3(KT, C), 128, smem_bytes>>>(queue, K, KT);
    finalize_kernel<<<1, n>>>((float*)d_out, n, KT);
}

// round 2
// speedup vs baseline: 1.8799x; 1.8799x over previous
#include <cuda_runtime.h>
#include <math.h>

#define D_DIM   128
#define N_MAX   1024
#define C_MAX   128
#define RR      16          // row-chunk (register accumulators per thread-column)
#define NKB_MAX 16          // max k-blocks (K/512)

// -------- scratch (device globals; no allocations allowed) --------
__device__ float g_qa  [N_MAX * D_DIM];     // normalized anchor qa per row
__device__ float g_lpos[N_MAX];
__device__ float g_bb  [N_MAX];             // b_i = qa_i . wn_{c_i}
__device__ int   g_off [C_MAX + 1];
__device__ int   g_rows[N_MAX];
__device__ float g_pm  [N_MAX * NKB_MAX];   // partial max   per (row, kblock)
__device__ float g_ps  [N_MAX * NKB_MAX];   // partial sumexp per (row, kblock)

__device__ __forceinline__ float warpSum(float v) {
    #pragma unroll
    for (int o = 16; o; o >>= 1) v += __shfl_xor_sync(0xffffffffu, v, o);
    return v;
}
__device__ __forceinline__ float warpMax(float v) {
    #pragma unroll
    for (int o = 16; o; o >>= 1) v = fmaxf(v, __shfl_xor_sync(0xffffffffu, v, o));
    return v;
}
__device__ __forceinline__ float dot4(float4 a, float4 b) {
    return fmaf(a.x, b.x, fmaf(a.y, b.y, fmaf(a.z, b.z, a.w * b.w)));
}
__device__ __forceinline__ float invn(float ss) {
    return 1.f / fmaxf(sqrtf(ss), 1e-12f);
}

// ============ prep kernel: block 0 = group rows by class; blocks 1.. = per-row qa/l_pos/b ============
__global__ void prep_kernel(const float* __restrict__ q,
                            const float* __restrict__ k,
                            const float* __restrict__ weight,
                            const int*   __restrict__ lab32,
                            int n, int C) {
    const int t = threadIdx.x;
    __shared__ int s_odd;
    if (t == 0) s_odd = 0;
    __syncthreads();
    // int64 vs int32 label detection: int64 (labels < 2^31) => all high words zero
    for (int i = t; i < n; i += blockDim.x)
        if (lab32[2 * i + 1] != 0) s_odd = 1;
    __syncthreads();
    const int stride = s_odd ? 1 : 2;

    if (blockIdx.x == 0) {
        __shared__ int cnt[C_MAX];
        __shared__ int base[C_MAX + 1];
        for (int c = t; c < C; c += blockDim.x) cnt[c] = 0;
        __syncthreads();
        for (int i = t; i < n; i += blockDim.x) atomicAdd(&cnt[lab32[i * stride]], 1);
        __syncthreads();
        if (t == 0) {
            base[0] = 0;
            for (int c = 0; c < C; ++c) base[c + 1] = base[c] + cnt[c];
        }
        __syncthreads();
        for (int c = t; c <= C; c += blockDim.x) g_off[c] = base[c];
        for (int c = t; c < C; c += blockDim.x) cnt[c] = 0;
        __syncthreads();
        for (int i = t; i < n; i += blockDim.x) {
            int c = lab32[i * stride];
            int p = base[c] + atomicAdd(&cnt[c], 1);
            g_rows[p] = i;
        }
    } else {
        // warp-per-row: 8 rows per block
        const int wid = t >> 5, lane = t & 31;
        const int i = (blockIdx.x - 1) * 8 + wid;
        if (i < n) {
            int c = lab32[i * stride];
            float4 w4 = ((const float4*)(weight + (size_t)c * D_DIM))[lane];
            float4 q4 = ((const float4*)(q + (size_t)i * D_DIM))[lane];
            float4 k4 = ((const float4*)(k + (size_t)i * D_DIM))[lane];
            float iw = invn(warpSum(dot4(w4, w4)));
            float4 wn = make_float4(w4.x * iw, w4.y * iw, w4.z * iw, w4.w * iw);
            float iq = invn(warpSum(dot4(q4, q4)));
            float ik = invn(warpSum(dot4(k4, k4)));
            float4 aq = make_float4(q4.x * iq - wn.x, q4.y * iq - wn.y,
                                    q4.z * iq - wn.z, q4.w * iq - wn.w);
            float4 ak = make_float4(k4.x * ik - wn.x, k4.y * ik - wn.y,
                                    k4.z * ik - wn.z, k4.w * ik - wn.w);
            float ia = invn(warpSum(dot4(aq, aq)));
            float ib = invn(warpSum(dot4(ak, ak)));
            float4 qa = make_float4(aq.x * ia, aq.y * ia, aq.z * ia, aq.w * ia);
            float4 ka = make_float4(ak.x * ib, ak.y * ib, ak.z * ib, ak.w * ib);
            ((float4*)(g_qa + (size_t)i * D_DIM))[lane] = qa;
            float lp = warpSum(dot4(qa, ka));
            float bv = warpSum(dot4(qa, wn));
            if (lane == 0) { g_lpos[i] = lp; g_bb[i] = bv; }
        }
    }
}

// ============ main kernel: streaming grouped GEMV over queue ============
// grid = (K/512, C), 256 threads; thread owns 2 adjacent columns (float2 loads).
// For each class row-chunk of RR, accumulate qa.x dots + column stats in registers
// while streaming queue straight from global (no tile staging).
template<int KC>
__global__ void __launch_bounds__(256, 3)
main_kernel(const float* __restrict__ queue,
            const float* __restrict__ weight,
            int Krt, int NKB) {
    const int K = (KC > 0) ? KC : Krt;
    const int c = blockIdx.y;
    const int off = g_off[c];
    const int nc  = g_off[c + 1] - off;
    if (nc == 0) return;
    const int t = threadIdx.x, lane = t & 31, wid = t >> 5;

    __shared__ float4 wn4s[32];
    __shared__ float  s_w2;
    __shared__ float4 qa4[RR * 32];
    __shared__ float  bs[RR];
    __shared__ int    ris[RR];
    __shared__ float  red_m[RR][8];
    __shared__ float  red_s[RR][8];

    if (wid == 0) {
        float4 w4 = ((const float4*)(weight + (size_t)c * D_DIM))[lane];
        float ssw = warpSum(dot4(w4, w4));
        float iw = invn(ssw);
        wn4s[lane] = make_float4(w4.x * iw, w4.y * iw, w4.z * iw, w4.w * iw);
        if (lane == 0) s_w2 = ssw * iw * iw;
    }

    const int KH = K >> 1;  // float2 stride per d
    const float2* const base =
        ((const float2*)(queue + (size_t)c * D_DIM * K + (size_t)blockIdx.x * 512)) + t;
    const float invT = 1.f / 0.07f;

    __syncthreads();
    const float w2 = s_w2;

    for (int r0 = 0; r0 < nc; r0 += RR) {
        const int rn = min(RR, nc - r0);

        if (t < RR) ris[t] = (t < rn) ? g_rows[off + r0 + t] : 0;
        __syncthreads();
        // gather qa rows into smem (zero-padded)
        #pragma unroll
        for (int it = 0; it < 2; ++it) {
            int idx = t + it * 256;          // RR*32 = 512
            int r = idx >> 5, c4 = idx & 31;
            float4 v = make_float4(0.f, 0.f, 0.f, 0.f);
            if (r < rn) v = ((const float4*)(g_qa + (size_t)ris[r] * D_DIM))[c4];
            qa4[r * 32 + c4] = v;
        }
        if (t < RR) bs[t] = (t < rn) ? g_bb[ris[t]] : 0.f;
        __syncthreads();

        float2 acc[RR];
        #pragma unroll
        for (int r = 0; r < RR; ++r) acc[r] = make_float2(0.f, 0.f);
        float2 ss = make_float2(0.f, 0.f);
        float2 sd = make_float2(0.f, 0.f);

        const float2* p = base;
        #pragma unroll 2
        for (int d4 = 0; d4 < 32; ++d4) {
            float2 v0 = p[0];
            float2 v1 = p[KH];
            float2 v2 = p[2 * KH];
            float2 v3 = p[3 * KH];
            p += 4 * KH;
            float4 w4 = wn4s[d4];
            ss.x = fmaf(v0.x, v0.x, fmaf(v1.x, v1.x, fmaf(v2.x, v2.x, fmaf(v3.x, v3.x, ss.x))));
            ss.y = fmaf(v0.y, v0.y, fmaf(v1.y, v1.y, fmaf(v2.y, v2.y, fmaf(v3.y, v3.y, ss.y))));
            sd.x = fmaf(w4.x, v0.x, fmaf(w4.y, v1.x, fmaf(w4.z, v2.x, fmaf(w4.w, v3.x, sd.x))));
            sd.y = fmaf(w4.x, v0.y, fmaf(w4.y, v1.y, fmaf(w4.z, v2.y, fmaf(w4.w, v3.y, sd.y))));
            #pragma unroll
            for (int r = 0; r < RR; ++r) {
                float4 qv = qa4[r * 32 + d4];
                acc[r].x = fmaf(qv.x, v0.x, fmaf(qv.y, v1.x, fmaf(qv.z, v2.x, fmaf(qv.w, v3.x, acc[r].x))));
                acc[r].y = fmaf(qv.x, v0.y, fmaf(qv.y, v1.y, fmaf(qv.z, v2.y, fmaf(qv.w, v3.y, acc[r].y))));
            }
        }

        // per-column scale factors
        float in0 = invn(ss.x), in1 = invn(ss.y);
        float na0 = fmaf(ss.x * in0, in0, fmaf(-2.f * sd.x, in0, w2));
        float na1 = fmaf(ss.y * in1, in1, fmaf(-2.f * sd.y, in1, w2));
        float id0 = invn(fmaxf(na0, 0.f));
        float id1 = invn(fmaxf(na1, 0.f));
        float sA0 = in0 * id0 * invT, sB0 = id0 * invT;
        float sA1 = in1 * id1 * invT, sB1 = id1 * invT;

        // per-row partial (max, sumexp) over this block's 512 columns
        #pragma unroll
        for (int r = 0; r < RR; ++r) {
            float b = bs[r];
            float l0 = fmaf(acc[r].x, sA0, -b * sB0);
            float l1 = fmaf(acc[r].y, sA1, -b * sB1);
            float m = warpMax(fmaxf(l0, l1));
            float s = warpSum(__expf(l0 - m) + __expf(l1 - m));
            if (lane == 0) { red_m[r][wid] = m; red_s[r][wid] = s; }
        }
        __syncthreads();
        if (t < RR && t < rn) {
            int r = t;
            float M = red_m[r][0];
            #pragma unroll
            for (int w = 1; w < 8; ++w) M = fmaxf(M, red_m[r][w]);
            float S = 0.f;
            #pragma unroll
            for (int w = 0; w < 8; ++w) S += red_s[r][w] * __expf(red_m[r][w] - M);
            int ri = ris[r];
            g_pm[ri * NKB + blockIdx.x] = M;
            g_ps[ri * NKB + blockIdx.x] = S;
        }
        __syncthreads();
    }
}

// ============ finalize: combine partials, logsumexp, mean ============
__global__ void finalize_kernel(float* __restrict__ out, int n, int NKB) {
    int t = threadIdx.x;
    const float invT = 1.f / 0.07f;
    float li = 0.f;
    if (t < n) {
        float lp = g_lpos[t] * invT;
        float M = lp;
        for (int j = 0; j < NKB; ++j) M = fmaxf(M, g_pm[t * NKB + j]);
        float S = expf(lp - M);
        for (int j = 0; j < NKB; ++j) S += g_ps[t * NKB + j] * expf(g_pm[t * NKB + j] - M);
        li = logf(S) + M - lp;
    }
    __shared__ float sm[32];
    float v = warpSum(li);
    if ((t & 31) == 0) sm[t >> 5] = v;
    __syncthreads();
    if (t < 32) {
        int nw = (blockDim.x + 31) >> 5;
        float x = (t < nw) ? sm[t] : 0.f;
        x = warpSum(x);
        if (t == 0) out[0] = x / (float)n;
    }
}

extern "C" void kernel_launch(void* const* d_in, const int* in_sizes, int n_in,
                              void* d_out, int out_size) {
    const float* q      = (const float*)d_in[0];
    const float* k      = (const float*)d_in[1];
    const float* weight = (const float*)d_in[2];
    const int*   lab32  = (const int*)d_in[3];
    const float* queue  = (const float*)d_in[4];

    int n  = in_sizes[0] / D_DIM;                 // 1024
    int C  = in_sizes[2] / D_DIM;                 // 100
    long long qe = in_sizes[4];
    int K  = (int)(qe / ((long long)C * D_DIM));  // 4096
    int NKB = K / 512;                            // 8

    int prep_blocks = 1 + (n + 7) / 8;
    prep_kernel<<<prep_blocks, 256>>>(q, k, weight, lab32, n, C);
    if (K == 4096)
        main_kernel<4096><<<dim3(NKB, C), 256>>>(queue, weight, K, NKB);
    else
        main_kernel<0><<<dim3(NKB, C), 256>>>(queue, weight, K, NKB);
    finalize_kernel<<<1, 1024>>>((float*)d_out, n, NKB);
}